// round 4
// baseline (speedup 1.0000x reference)
#include <cuda_runtime.h>
#include <cuda_bf16.h>
#include <float.h>
#include <stdint.h>

#define BSZ 16
#define NP  4096
#define ND  256
#define NC  512
#define MARGIN 1e-3f

#define NSLICE 8
#define SLICE_P (NP / NSLICE)   // 512
#define MAXC 6
#define LDT 72                  // smem chunk pitch (64 + 8 pad) in bf16 elems

// ---- scratch (static device memory; no runtime allocation) ----
__device__ __nv_bfloat16 g_xbf[(size_t)BSZ * NP * ND];     // 33.5 MB
__device__ __nv_bfloat16 g_kbf[NC * ND];                    // 256 KB
__device__ float g_scores[(size_t)BSZ * NP * NC];           // 134 MB
__device__ float g_smax[BSZ * NSLICE * NC];
__device__ int   g_scnt[BSZ * NSLICE * NC];
__device__ float g_cval[BSZ * NSLICE * NC * MAXC];
__device__ int   g_cpos[BSZ * NSLICE * NC * MAXC];
__device__ int   g_bestidx[BSZ * NC];

// ---------------------------------------------------------------------------
__global__ void zero_kernel(float4* __restrict__ out, int n4) {
    int i = blockIdx.x * blockDim.x + threadIdx.x;
    float4 z = make_float4(0.f, 0.f, 0.f, 0.f);
    for (; i < n4; i += gridDim.x * blockDim.x) out[i] = z;
}

// ---------------------------------------------------------------------------
// fp32 -> bf16 conversion of x and kernels
// ---------------------------------------------------------------------------
__global__ void convert_kernel(const float* __restrict__ x,
                               const float* __restrict__ kern) {
    const int NX4 = BSZ * NP * ND / 4;   // 4,194,304
    const int NK4 = NC * ND / 4;         // 32,768
    int i = blockIdx.x * blockDim.x + threadIdx.x;
    if (i < NX4) {
        float4 v = ((const float4*)x)[i];
        ((__nv_bfloat162*)g_xbf)[i * 2]     = __floats2bfloat162_rn(v.x, v.y);
        ((__nv_bfloat162*)g_xbf)[i * 2 + 1] = __floats2bfloat162_rn(v.z, v.w);
    } else if (i < NX4 + NK4) {
        int j = i - NX4;
        float4 v = ((const float4*)kern)[j];
        ((__nv_bfloat162*)g_kbf)[j * 2]     = __floats2bfloat162_rn(v.x, v.y);
        ((__nv_bfloat162*)g_kbf)[j * 2 + 1] = __floats2bfloat162_rn(v.z, v.w);
    }
}

// ---------------------------------------------------------------------------
// bf16 tensor-core GEMM: scores[b][p][c] = x[b,p,:] . kernels[c,:]
// Block tile 128x128, K staged in 4 chunks of 64 with cp.async double buffer.
// 8 warps: 2(m) x 4(n), warp tile 64x32, mma.m16n8k16 bf16 -> fp32.
// ---------------------------------------------------------------------------
__global__ __launch_bounds__(256)
void gemm_kernel() {
    extern __shared__ __nv_bfloat16 sm[];
    __nv_bfloat16* As = sm;                    // [2][128*LDT]
    __nv_bfloat16* Bs = sm + 2 * 128 * LDT;    // [2][128*LDT]

    const int b = blockIdx.z, mt = blockIdx.y, nt = blockIdx.x;
    const int tid = threadIdx.x, lane = tid & 31, warp = tid >> 5;
    const int wm = warp & 1, wn = warp >> 1;

    const __nv_bfloat16* Ag = g_xbf + ((size_t)b * NP + mt * 128) * ND;
    const __nv_bfloat16* Bg = g_kbf + (size_t)nt * 128 * ND;

    float acc[4][4][4];
    #pragma unroll
    for (int i = 0; i < 4; ++i)
        #pragma unroll
        for (int j = 0; j < 4; ++j)
            #pragma unroll
            for (int q = 0; q < 4; ++q) acc[i][j][q] = 0.f;

    // async stage loader: k-chunk kc -> stage st
    auto issue = [&](int kc, int st) {
        int base = st * 128 * LDT;
        #pragma unroll
        for (int it = 0; it < 4; ++it) {
            int i = it * 256 + tid;
            int r = i >> 3, c = (i & 7) * 8;
            uint32_t sa = (uint32_t)__cvta_generic_to_shared(&As[base + r * LDT + c]);
            const __nv_bfloat16* ga = Ag + (size_t)r * ND + kc * 64 + c;
            asm volatile("cp.async.cg.shared.global [%0], [%1], 16;" :: "r"(sa), "l"(ga) : "memory");
            uint32_t sb = (uint32_t)__cvta_generic_to_shared(&Bs[base + r * LDT + c]);
            const __nv_bfloat16* gb = Bg + (size_t)r * ND + kc * 64 + c;
            asm volatile("cp.async.cg.shared.global [%0], [%1], 16;" :: "r"(sb), "l"(gb) : "memory");
        }
        asm volatile("cp.async.commit_group;" ::: "memory");
    };

    issue(0, 0);
    issue(1, 1);

    const int lm = lane & 15, lk = (lane >> 4) * 8;

    #pragma unroll
    for (int kc = 0; kc < 4; ++kc) {
        if (kc < 3) asm volatile("cp.async.wait_group 1;" ::: "memory");
        else        asm volatile("cp.async.wait_group 0;" ::: "memory");
        __syncthreads();

        int st = kc & 1;
        const __nv_bfloat16* Ab = As + st * 128 * LDT + wm * 64 * LDT;
        const __nv_bfloat16* Bb = Bs + st * 128 * LDT + wn * 32 * LDT;

        #pragma unroll
        for (int ks = 0; ks < 4; ++ks) {
            uint32_t af[4][4], bfv[2][4];
            #pragma unroll
            for (int i = 0; i < 4; ++i) {
                uint32_t addr = (uint32_t)__cvta_generic_to_shared(
                    Ab + (i * 16 + lm) * LDT + ks * 16 + lk);
                asm volatile("ldmatrix.sync.aligned.m8n8.x4.shared.b16 {%0,%1,%2,%3}, [%4];"
                    : "=r"(af[i][0]), "=r"(af[i][1]), "=r"(af[i][2]), "=r"(af[i][3])
                    : "r"(addr));
            }
            // B tile is [channel][k] row-major = exactly the n8k16 col-major
            // operand fragment under a NON-transposed ldmatrix (n = lane/4,
            // consecutive k pair per register).
            #pragma unroll
            for (int j = 0; j < 2; ++j) {
                uint32_t addr = (uint32_t)__cvta_generic_to_shared(
                    Bb + (j * 16 + lm) * LDT + ks * 16 + lk);
                asm volatile("ldmatrix.sync.aligned.m8n8.x4.shared.b16 {%0,%1,%2,%3}, [%4];"
                    : "=r"(bfv[j][0]), "=r"(bfv[j][1]), "=r"(bfv[j][2]), "=r"(bfv[j][3])
                    : "r"(addr));
            }
            #pragma unroll
            for (int i = 0; i < 4; ++i)
                #pragma unroll
                for (int j = 0; j < 4; ++j) {
                    uint32_t b0 = bfv[j >> 1][(j & 1)];
                    uint32_t b1 = bfv[j >> 1][(j & 1) + 2];
                    asm volatile(
                        "mma.sync.aligned.m16n8k16.row.col.f32.bf16.bf16.f32 "
                        "{%0,%1,%2,%3}, {%4,%5,%6,%7}, {%8,%9}, {%0,%1,%2,%3};"
                        : "+f"(acc[i][j][0]), "+f"(acc[i][j][1]),
                          "+f"(acc[i][j][2]), "+f"(acc[i][j][3])
                        : "r"(af[i][0]), "r"(af[i][1]), "r"(af[i][2]), "r"(af[i][3]),
                          "r"(b0), "r"(b1));
                }
        }
        __syncthreads();
        if (kc + 2 < 4) issue(kc + 2, st);
    }

    // epilogue: store fp32 scores [b][p][c]
    const int p0 = mt * 128 + wm * 64, c0 = nt * 128 + wn * 32;
    float* sc = g_scores + (size_t)b * NP * NC;
    const int gq = lane >> 2, q2 = (lane & 3) * 2;
    #pragma unroll
    for (int i = 0; i < 4; ++i)
        #pragma unroll
        for (int j = 0; j < 4; ++j) {
            int p = p0 + i * 16 + gq, c = c0 + j * 8 + q2;
            *(float2*)&sc[(size_t)p * NC + c]       = make_float2(acc[i][j][0], acc[i][j][1]);
            *(float2*)&sc[(size_t)(p + 8) * NC + c] = make_float2(acc[i][j][2], acc[i][j][3]);
        }
}

// ---------------------------------------------------------------------------
// Per-slice scan: running max + candidates within MARGIN of running max.
// grid (NSLICE, BSZ), block = 512 threads (one per channel). Coalesced reads.
// ---------------------------------------------------------------------------
__global__ void scan_kernel() {
    int b = blockIdx.y, s = blockIdx.x, c = threadIdx.x;
    const float* sc = g_scores + ((size_t)b * NP + s * SLICE_P) * NC + c;

    float bm = -FLT_MAX;
    float cv[8]; int cp[8]; int ncand = 0;

    #pragma unroll 4
    for (int p = 0; p < SLICE_P; ++p) {
        float v = __ldg(&sc[(size_t)p * NC]);
        if (v > bm) bm = v;
        if (v > bm - MARGIN) {
            if (ncand == 8) {   // compact against current running max
                int m = 0;
                for (int i = 0; i < 8; ++i)
                    if (cv[i] > bm - MARGIN) { cv[m] = cv[i]; cp[m] = cp[i]; ++m; }
                ncand = m;
            }
            if (ncand < 8) { cv[ncand] = v; cp[ncand] = s * SLICE_P + p; ++ncand; }
        }
    }

    int o = (b * NSLICE + s) * NC + c;
    g_smax[o] = bm;
    int m = 0;
    for (int i = 0; i < ncand && m < MAXC; ++i)
        if (cv[i] > bm - MARGIN) {
            g_cval[o * MAXC + m] = cv[i];
            g_cpos[o * MAXC + m] = cp[i];
            ++m;
        }
    g_scnt[o] = m;
}

// ---------------------------------------------------------------------------
// Merge slices + exact fp32 rescore of every candidate within MARGIN of the
// global coarse max. Exactness restores fp32-grade argmax.
// ---------------------------------------------------------------------------
__global__ void merge_kernel(const float* __restrict__ x,
                             const float* __restrict__ kern) {
    int t = blockIdx.x * blockDim.x + threadIdx.x;
    if (t >= BSZ * NC) return;
    int b = t / NC, c = t % NC;

    float gmax = -FLT_MAX;
    #pragma unroll
    for (int s = 0; s < NSLICE; ++s)
        gmax = fmaxf(gmax, g_smax[(b * NSLICE + s) * NC + c]);

    float bestv = -FLT_MAX; int bestp = 0; bool have = false;
    const float* kr = kern + (size_t)c * ND;

    for (int s = 0; s < NSLICE; ++s) {
        int o = (b * NSLICE + s) * NC + c;
        int n = g_scnt[o];
        for (int i = 0; i < n; ++i) {
            float cvv = g_cval[o * MAXC + i];
            if (cvv > gmax - MARGIN) {
                int p = g_cpos[o * MAXC + i];
                const float* xr = x + ((size_t)b * NP + p) * ND;
                float sum = 0.f;
                #pragma unroll 8
                for (int d = 0; d < ND; d += 4) {
                    float4 xv = *(const float4*)&xr[d];
                    float4 kv = *(const float4*)&kr[d];
                    sum += xv.x * kv.x + xv.y * kv.y + xv.z * kv.z + xv.w * kv.w;
                }
                if (!have || sum > bestv || (sum == bestv && p < bestp)) {
                    bestv = sum; bestp = p; have = true;
                }
            }
        }
    }
    if (bestv <= 0.f) bestp = 0;   // all-ReLU-zero => argmax = 0
    g_bestidx[t] = bestp;
}

// ---------------------------------------------------------------------------
__global__ void scatter_kernel(const float* __restrict__ kern, float* __restrict__ out) {
    int task = blockIdx.x * 8 + (threadIdx.x >> 5);
    int lane = threadIdx.x & 31;
    int b = task >> 9;
    int c = task & (NC - 1);
    int p = g_bestidx[task];
    float*       dst = out  + ((size_t)(b * NP + p)) * ND;
    const float* src = kern + (size_t)c * ND;
    #pragma unroll
    for (int d = lane; d < ND; d += 32)
        atomicAdd(&dst[d], src[d]);
}

// ---------------------------------------------------------------------------
extern "C" void kernel_launch(void* const* d_in, const int* in_sizes, int n_in,
                              void* d_out, int out_size) {
    const float* x    = (const float*)d_in[0];
    const float* kern = (const float*)d_in[1];
    float*       out  = (float*)d_out;

    zero_kernel<<<4096, 256>>>((float4*)out, BSZ * NP * ND / 4);

    convert_kernel<<<16513, 256>>>(x, kern);

    size_t smem = 2 * 2 * 128 * LDT * sizeof(__nv_bfloat16);   // 73,728 B
    cudaFuncSetAttribute(gemm_kernel,
                         cudaFuncAttributeMaxDynamicSharedMemorySize, (int)smem);
    gemm_kernel<<<dim3(4, 32, 16), 256, smem>>>();

    scan_kernel<<<dim3(NSLICE, BSZ), NC>>>();

    merge_kernel<<<32, 256>>>(x, kern);

    scatter_kernel<<<BSZ * NC / 8, 256>>>(kern, out);
}

// round 5
// speedup vs baseline: 3.3790x; 3.3790x over previous
#include <cuda_runtime.h>
#include <cuda_bf16.h>
#include <float.h>
#include <stdint.h>

#define BSZ 16
#define NP  4096
#define ND  256
#define NC  512
#define MARGIN 1e-3f

#define NMT  32                 // m-tiles per batch (slices)
#define MAXC 4
#define LDT  72                 // smem chunk pitch (64 + 8 pad) in bf16 elems

// ---- scratch (static device memory) ----
__device__ __nv_bfloat16 g_xbf[(size_t)BSZ * NP * ND];   // 33.5 MB
__device__ __nv_bfloat16 g_kbf[NC * ND];                  // 256 KB
__device__ float g_smax[BSZ * NMT * NC];                  // per (b, mt, c) block max
__device__ int   g_scnt[BSZ * NMT * NC];
__device__ float g_cval[(size_t)BSZ * NMT * NC * MAXC];
__device__ int   g_cpos[(size_t)BSZ * NMT * NC * MAXC];
__device__ int   g_bestidx[BSZ * NC];

// ---------------------------------------------------------------------------
__global__ void zero_kernel(float4* __restrict__ out, int n4) {
    int i = blockIdx.x * blockDim.x + threadIdx.x;
    float4 z = make_float4(0.f, 0.f, 0.f, 0.f);
    for (; i < n4; i += gridDim.x * blockDim.x) out[i] = z;
}

// ---------------------------------------------------------------------------
__global__ void convert_kernel(const float* __restrict__ x,
                               const float* __restrict__ kern) {
    const int NX4 = BSZ * NP * ND / 4;
    const int NK4 = NC * ND / 4;
    int i = blockIdx.x * blockDim.x + threadIdx.x;
    if (i < NX4) {
        float4 v = ((const float4*)x)[i];
        ((__nv_bfloat162*)g_xbf)[i * 2]     = __floats2bfloat162_rn(v.x, v.y);
        ((__nv_bfloat162*)g_xbf)[i * 2 + 1] = __floats2bfloat162_rn(v.z, v.w);
    } else if (i < NX4 + NK4) {
        int j = i - NX4;
        float4 v = ((const float4*)kern)[j];
        ((__nv_bfloat162*)g_kbf)[j * 2]     = __floats2bfloat162_rn(v.x, v.y);
        ((__nv_bfloat162*)g_kbf)[j * 2 + 1] = __floats2bfloat162_rn(v.z, v.w);
    }
}

// ---------------------------------------------------------------------------
// bf16 tensor GEMM 128x128 tile + FUSED per-channel argmax/candidate epilogue.
// Grid (nt=4, mt=32, b=16), 256 threads, warps 2(m) x 4(n), warp tile 64x32.
// ---------------------------------------------------------------------------
__global__ __launch_bounds__(256)
void gemm_kernel() {
    extern __shared__ __nv_bfloat16 sm[];
    __nv_bfloat16* As = sm;                    // [2][128*LDT]
    __nv_bfloat16* Bs = sm + 2 * 128 * LDT;    // [2][128*LDT]

    const int b = blockIdx.z, mt = blockIdx.y, nt = blockIdx.x;
    const int tid = threadIdx.x, lane = tid & 31, warp = tid >> 5;
    const int wm = warp & 1, wn = warp >> 1;

    const __nv_bfloat16* Ag = g_xbf + ((size_t)b * NP + mt * 128) * ND;
    const __nv_bfloat16* Bg = g_kbf + (size_t)nt * 128 * ND;

    float acc[4][4][4];
    #pragma unroll
    for (int i = 0; i < 4; ++i)
        #pragma unroll
        for (int j = 0; j < 4; ++j)
            #pragma unroll
            for (int q = 0; q < 4; ++q) acc[i][j][q] = 0.f;

    auto issue = [&](int kc, int st) {
        int base = st * 128 * LDT;
        #pragma unroll
        for (int it = 0; it < 4; ++it) {
            int i = it * 256 + tid;
            int r = i >> 3, c = (i & 7) * 8;
            uint32_t sa = (uint32_t)__cvta_generic_to_shared(&As[base + r * LDT + c]);
            const __nv_bfloat16* ga = Ag + (size_t)r * ND + kc * 64 + c;
            asm volatile("cp.async.cg.shared.global [%0], [%1], 16;" :: "r"(sa), "l"(ga) : "memory");
            uint32_t sb = (uint32_t)__cvta_generic_to_shared(&Bs[base + r * LDT + c]);
            const __nv_bfloat16* gb = Bg + (size_t)r * ND + kc * 64 + c;
            asm volatile("cp.async.cg.shared.global [%0], [%1], 16;" :: "r"(sb), "l"(gb) : "memory");
        }
        asm volatile("cp.async.commit_group;" ::: "memory");
    };

    issue(0, 0);
    issue(1, 1);

    const int lm = lane & 15, lk = (lane >> 4) * 8;

    #pragma unroll
    for (int kc = 0; kc < 4; ++kc) {
        if (kc < 3) asm volatile("cp.async.wait_group 1;" ::: "memory");
        else        asm volatile("cp.async.wait_group 0;" ::: "memory");
        __syncthreads();

        int st = kc & 1;
        const __nv_bfloat16* Ab = As + st * 128 * LDT + wm * 64 * LDT;
        const __nv_bfloat16* Bb = Bs + st * 128 * LDT + wn * 32 * LDT;

        #pragma unroll
        for (int ks = 0; ks < 4; ++ks) {
            uint32_t af[4][4], bfv[2][4];
            #pragma unroll
            for (int i = 0; i < 4; ++i) {
                uint32_t addr = (uint32_t)__cvta_generic_to_shared(
                    Ab + (i * 16 + lm) * LDT + ks * 16 + lk);
                asm volatile("ldmatrix.sync.aligned.m8n8.x4.shared.b16 {%0,%1,%2,%3}, [%4];"
                    : "=r"(af[i][0]), "=r"(af[i][1]), "=r"(af[i][2]), "=r"(af[i][3])
                    : "r"(addr));
            }
            #pragma unroll
            for (int j = 0; j < 2; ++j) {
                uint32_t addr = (uint32_t)__cvta_generic_to_shared(
                    Bb + (j * 16 + lm) * LDT + ks * 16 + lk);
                asm volatile("ldmatrix.sync.aligned.m8n8.x4.shared.b16 {%0,%1,%2,%3}, [%4];"
                    : "=r"(bfv[j][0]), "=r"(bfv[j][1]), "=r"(bfv[j][2]), "=r"(bfv[j][3])
                    : "r"(addr));
            }
            #pragma unroll
            for (int i = 0; i < 4; ++i)
                #pragma unroll
                for (int j = 0; j < 4; ++j) {
                    uint32_t b0 = bfv[j >> 1][(j & 1)];
                    uint32_t b1 = bfv[j >> 1][(j & 1) + 2];
                    asm volatile(
                        "mma.sync.aligned.m16n8k16.row.col.f32.bf16.bf16.f32 "
                        "{%0,%1,%2,%3}, {%4,%5,%6,%7}, {%8,%9}, {%0,%1,%2,%3};"
                        : "+f"(acc[i][j][0]), "+f"(acc[i][j][1]),
                          "+f"(acc[i][j][2]), "+f"(acc[i][j][3])
                        : "r"(af[i][0]), "r"(af[i][1]), "r"(af[i][2]), "r"(af[i][3]),
                          "r"(b0), "r"(b1));
                }
        }
        __syncthreads();
        if (kc + 2 < 4) issue(kc + 2, st);
    }

    // ================= fused epilogue: per-channel block argmax ==============
    // smem reuse (all reads of As/Bs done; the last loop iteration ended with
    // __syncthreads()).
    float* sval = (float*)sm;                    // [128][17]
    int*   sidx = (int*)(sval + 128 * 17);       // [128][17]
    float* sbm  = (float*)(sidx + 128 * 17);     // [128]
    int*   scnt = (int*)(sbm + 128);             // [128]
    float* scv  = (float*)(scnt + 128);          // [128][MAXC]
    int*   scp  = (int*)(scv + 128 * MAXC);      // [128][MAXC]

    const int gq = lane >> 2, q2 = (lane & 3) * 2;
    const int rowgrp = wm * 8 + gq;
    const int pbase  = mt * 128 + wm * 64;       // global p of (i=0,gq=0) row - gq

    // pass 1: per-thread partial (max, idx) per channel
    #pragma unroll
    for (int j = 0; j < 4; ++j)
        #pragma unroll
        for (int e = 0; e < 2; ++e) {
            int ch = wn * 32 + j * 8 + q2 + e;
            float m = -FLT_MAX; int mi = 0;
            #pragma unroll
            for (int i = 0; i < 4; ++i) {
                int p0 = pbase + i * 16 + gq;
                float v0 = acc[i][j][e];
                float v1 = acc[i][j][e + 2];
                if (v0 > m) { m = v0; mi = p0; }
                if (v1 > m) { m = v1; mi = p0 + 8; }
            }
            sval[ch * 17 + rowgrp] = m;
            sidx[ch * 17 + rowgrp] = mi;
        }
    __syncthreads();

    // reduce 16 partials per channel; init candidate counters
    if (tid < 128) {
        float bv = -FLT_MAX; int bi = 0;
        #pragma unroll
        for (int r = 0; r < 16; ++r) {
            float v  = sval[tid * 17 + r];
            int   ii = sidx[tid * 17 + r];
            if (v > bv || (v == bv && ii < bi)) { bv = v; bi = ii; }
        }
        sbm[tid]  = bv;
        scnt[tid] = 0;
    }
    __syncthreads();

    // pass 2: collect candidates within MARGIN of block max
    #pragma unroll
    for (int j = 0; j < 4; ++j)
        #pragma unroll
        for (int e = 0; e < 2; ++e) {
            int ch = wn * 32 + j * 8 + q2 + e;
            float thr = sbm[ch] - MARGIN;
            #pragma unroll
            for (int i = 0; i < 4; ++i) {
                int p0 = pbase + i * 16 + gq;
                float v0 = acc[i][j][e];
                float v1 = acc[i][j][e + 2];
                if (v0 > thr) {
                    int slot = atomicAdd(&scnt[ch], 1);
                    if (slot < MAXC) { scv[ch * MAXC + slot] = v0; scp[ch * MAXC + slot] = p0; }
                }
                if (v1 > thr) {
                    int slot = atomicAdd(&scnt[ch], 1);
                    if (slot < MAXC) { scv[ch * MAXC + slot] = v1; scp[ch * MAXC + slot] = p0 + 8; }
                }
            }
        }
    __syncthreads();

    // write per-(b, mt, channel) summary to global
    if (tid < 128) {
        int o = (b * NMT + mt) * NC + nt * 128 + tid;
        int n = min(scnt[tid], MAXC);
        g_smax[o] = sbm[tid];
        g_scnt[o] = n;
        for (int i = 0; i < n; ++i) {
            g_cval[(size_t)o * MAXC + i] = scv[tid * MAXC + i];
            g_cpos[(size_t)o * MAXC + i] = scp[tid * MAXC + i];
        }
    }
}

// ---------------------------------------------------------------------------
// Merge: warp per (b,c). Global coarse max over 32 m-tiles, exact fp32
// rescore of all candidates within MARGIN of it, first-occurrence tie-break.
// ---------------------------------------------------------------------------
__global__ __launch_bounds__(256)
void merge_kernel(const float* __restrict__ x, const float* __restrict__ kern) {
    int task = blockIdx.x * 8 + (threadIdx.x >> 5);   // 1024 blocks * 8 warps = 8192
    int lane = threadIdx.x & 31;
    int b = task >> 9, c = task & (NC - 1);

    // gmax: lane l reads m-tile l's max
    float m = g_smax[(b * NMT + lane) * NC + c];
    #pragma unroll
    for (int o = 16; o > 0; o >>= 1)
        m = fmaxf(m, __shfl_xor_sync(0xffffffffu, m, o));
    const float thr = m - MARGIN;

    const float* kr = kern + (size_t)c * ND;
    float kx0, kx1;   // per-lane slice of kernel row (8 elems)
    float4 k4a = *(const float4*)&kr[lane * 8];
    float4 k4b = *(const float4*)&kr[lane * 8 + 4];

    float bestv = -FLT_MAX; int bestp = 0x7fffffff; bool have = false;

    for (int s = 0; s < NMT; ++s) {
        int o = (b * NMT + s) * NC + c;
        int n = g_scnt[o];
        for (int i = 0; i < n; ++i) {
            float cvv = g_cval[(size_t)o * MAXC + i];
            if (cvv > thr) {
                int p = g_cpos[(size_t)o * MAXC + i];
                const float* xr = x + ((size_t)b * NP + p) * ND + lane * 8;
                float4 xa = *(const float4*)xr;
                float4 xb = *(const float4*)(xr + 4);
                float sum = xa.x * k4a.x + xa.y * k4a.y + xa.z * k4a.z + xa.w * k4a.w
                          + xb.x * k4b.x + xb.y * k4b.y + xb.z * k4b.z + xb.w * k4b.w;
                #pragma unroll
                for (int off = 16; off > 0; off >>= 1)
                    sum += __shfl_xor_sync(0xffffffffu, sum, off);
                if (!have || sum > bestv || (sum == bestv && p < bestp)) {
                    bestv = sum; bestp = p; have = true;
                }
            }
        }
    }
    if (bestv <= 0.f) bestp = 0;   // all-ReLU-zero => argmax = 0
    if (lane == 0) g_bestidx[task] = bestp;
    (void)kx0; (void)kx1;
}

// ---------------------------------------------------------------------------
__global__ void scatter_kernel(const float* __restrict__ kern, float* __restrict__ out) {
    int task = blockIdx.x * 8 + (threadIdx.x >> 5);
    int lane = threadIdx.x & 31;
    int b = task >> 9;
    int c = task & (NC - 1);
    int p = g_bestidx[task];
    float*       dst = out  + ((size_t)(b * NP + p)) * ND;
    const float* src = kern + (size_t)c * ND;
    #pragma unroll
    for (int d = lane; d < ND; d += 32)
        atomicAdd(&dst[d], src[d]);
}

// ---------------------------------------------------------------------------
extern "C" void kernel_launch(void* const* d_in, const int* in_sizes, int n_in,
                              void* d_out, int out_size) {
    const float* x    = (const float*)d_in[0];
    const float* kern = (const float*)d_in[1];
    float*       out  = (float*)d_out;

    zero_kernel<<<4096, 256>>>((float4*)out, BSZ * NP * ND / 4);

    convert_kernel<<<16513, 256>>>(x, kern);

    size_t smem = 2 * 2 * 128 * LDT * sizeof(__nv_bfloat16);   // 73,728 B
    cudaFuncSetAttribute(gemm_kernel,
                         cudaFuncAttributeMaxDynamicSharedMemorySize, (int)smem);
    gemm_kernel<<<dim3(4, NMT, BSZ), 256, smem>>>();

    merge_kernel<<<BSZ * NC / 8, 256>>>(x, kern);

    scatter_kernel<<<BSZ * NC / 8, 256>>>(kern, out);
}

// round 6
// speedup vs baseline: 4.5171x; 1.3368x over previous
#include <cuda_runtime.h>
#include <cuda_bf16.h>
#include <float.h>
#include <stdint.h>

#define BSZ 16
#define NP  4096
#define ND  256
#define NC  512
#define MARGIN 1e-3f

#define NMT  32                 // m-tiles per batch == warp size (by design)
#define MAXC 4
#define LDT  72                 // smem chunk pitch (64 + 8 pad) in bf16 elems

// ---- scratch (static device memory) ----
__device__ __nv_bfloat16 g_xbf[(size_t)BSZ * NP * ND];   // 33.5 MB
__device__ __nv_bfloat16 g_kbf[NC * ND];                  // 256 KB
__device__ float g_smax[BSZ * NMT * NC];
__device__ int   g_scnt[BSZ * NMT * NC];
__device__ float g_cval[(size_t)BSZ * NMT * NC * MAXC];
__device__ int   g_cpos[(size_t)BSZ * NMT * NC * MAXC];

// ---------------------------------------------------------------------------
__global__ void zero_kernel(float4* __restrict__ out, int n4) {
    int i = blockIdx.x * blockDim.x + threadIdx.x;
    float4 z = make_float4(0.f, 0.f, 0.f, 0.f);
    for (; i < n4; i += gridDim.x * blockDim.x) out[i] = z;
}

// ---------------------------------------------------------------------------
__global__ void convert_kernel(const float* __restrict__ x,
                               const float* __restrict__ kern) {
    const int NX4 = BSZ * NP * ND / 4;
    const int NK4 = NC * ND / 4;
    int i = blockIdx.x * blockDim.x + threadIdx.x;
    if (i < NX4) {
        float4 v = ((const float4*)x)[i];
        ((__nv_bfloat162*)g_xbf)[i * 2]     = __floats2bfloat162_rn(v.x, v.y);
        ((__nv_bfloat162*)g_xbf)[i * 2 + 1] = __floats2bfloat162_rn(v.z, v.w);
    } else if (i < NX4 + NK4) {
        int j = i - NX4;
        float4 v = ((const float4*)kern)[j];
        ((__nv_bfloat162*)g_kbf)[j * 2]     = __floats2bfloat162_rn(v.x, v.y);
        ((__nv_bfloat162*)g_kbf)[j * 2 + 1] = __floats2bfloat162_rn(v.z, v.w);
    }
}

// ---------------------------------------------------------------------------
// bf16 tensor GEMM 128x128 tile + fused per-channel argmax/candidate epilogue.
// ---------------------------------------------------------------------------
__global__ __launch_bounds__(256)
void gemm_kernel() {
    extern __shared__ __nv_bfloat16 sm[];
    __nv_bfloat16* As = sm;                    // [2][128*LDT]
    __nv_bfloat16* Bs = sm + 2 * 128 * LDT;    // [2][128*LDT]

    const int b = blockIdx.z, mt = blockIdx.y, nt = blockIdx.x;
    const int tid = threadIdx.x, lane = tid & 31, warp = tid >> 5;
    const int wm = warp & 1, wn = warp >> 1;

    const __nv_bfloat16* Ag = g_xbf + ((size_t)b * NP + mt * 128) * ND;
    const __nv_bfloat16* Bg = g_kbf + (size_t)nt * 128 * ND;

    float acc[4][4][4];
    #pragma unroll
    for (int i = 0; i < 4; ++i)
        #pragma unroll
        for (int j = 0; j < 4; ++j)
            #pragma unroll
            for (int q = 0; q < 4; ++q) acc[i][j][q] = 0.f;

    auto issue = [&](int kc, int st) {
        int base = st * 128 * LDT;
        #pragma unroll
        for (int it = 0; it < 4; ++it) {
            int i = it * 256 + tid;
            int r = i >> 3, c = (i & 7) * 8;
            uint32_t sa = (uint32_t)__cvta_generic_to_shared(&As[base + r * LDT + c]);
            const __nv_bfloat16* ga = Ag + (size_t)r * ND + kc * 64 + c;
            asm volatile("cp.async.cg.shared.global [%0], [%1], 16;" :: "r"(sa), "l"(ga) : "memory");
            uint32_t sb = (uint32_t)__cvta_generic_to_shared(&Bs[base + r * LDT + c]);
            const __nv_bfloat16* gb = Bg + (size_t)r * ND + kc * 64 + c;
            asm volatile("cp.async.cg.shared.global [%0], [%1], 16;" :: "r"(sb), "l"(gb) : "memory");
        }
        asm volatile("cp.async.commit_group;" ::: "memory");
    };

    issue(0, 0);
    issue(1, 1);

    const int lm = lane & 15, lk = (lane >> 4) * 8;

    #pragma unroll
    for (int kc = 0; kc < 4; ++kc) {
        if (kc < 3) asm volatile("cp.async.wait_group 1;" ::: "memory");
        else        asm volatile("cp.async.wait_group 0;" ::: "memory");
        __syncthreads();

        int st = kc & 1;
        const __nv_bfloat16* Ab = As + st * 128 * LDT + wm * 64 * LDT;
        const __nv_bfloat16* Bb = Bs + st * 128 * LDT + wn * 32 * LDT;

        #pragma unroll
        for (int ks = 0; ks < 4; ++ks) {
            uint32_t af[4][4], bfv[2][4];
            #pragma unroll
            for (int i = 0; i < 4; ++i) {
                uint32_t addr = (uint32_t)__cvta_generic_to_shared(
                    Ab + (i * 16 + lm) * LDT + ks * 16 + lk);
                asm volatile("ldmatrix.sync.aligned.m8n8.x4.shared.b16 {%0,%1,%2,%3}, [%4];"
                    : "=r"(af[i][0]), "=r"(af[i][1]), "=r"(af[i][2]), "=r"(af[i][3])
                    : "r"(addr));
            }
            #pragma unroll
            for (int j = 0; j < 2; ++j) {
                uint32_t addr = (uint32_t)__cvta_generic_to_shared(
                    Bb + (j * 16 + lm) * LDT + ks * 16 + lk);
                asm volatile("ldmatrix.sync.aligned.m8n8.x4.shared.b16 {%0,%1,%2,%3}, [%4];"
                    : "=r"(bfv[j][0]), "=r"(bfv[j][1]), "=r"(bfv[j][2]), "=r"(bfv[j][3])
                    : "r"(addr));
            }
            #pragma unroll
            for (int i = 0; i < 4; ++i)
                #pragma unroll
                for (int j = 0; j < 4; ++j) {
                    uint32_t b0 = bfv[j >> 1][(j & 1)];
                    uint32_t b1 = bfv[j >> 1][(j & 1) + 2];
                    asm volatile(
                        "mma.sync.aligned.m16n8k16.row.col.f32.bf16.bf16.f32 "
                        "{%0,%1,%2,%3}, {%4,%5,%6,%7}, {%8,%9}, {%0,%1,%2,%3};"
                        : "+f"(acc[i][j][0]), "+f"(acc[i][j][1]),
                          "+f"(acc[i][j][2]), "+f"(acc[i][j][3])
                        : "r"(af[i][0]), "r"(af[i][1]), "r"(af[i][2]), "r"(af[i][3]),
                          "r"(b0), "r"(b1));
                }
        }
        __syncthreads();
        if (kc + 2 < 4) issue(kc + 2, st);
    }

    // ================= fused epilogue: per-channel block argmax ==============
    float* sval = (float*)sm;                    // [128][17]
    int*   sidx = (int*)(sval + 128 * 17);       // [128][17]
    float* sbm  = (float*)(sidx + 128 * 17);     // [128]
    int*   sbi  = (int*)(sbm + 128);             // [128]
    int*   scnt = (int*)(sbi + 128);             // [128]
    float* scv  = (float*)(scnt + 128);          // [128][MAXC]
    int*   scp  = (int*)(scv + 128 * MAXC);      // [128][MAXC]

    const int gq = lane >> 2, q2 = (lane & 3) * 2;
    const int rowgrp = wm * 8 + gq;
    const int pbase  = mt * 128 + wm * 64;

    // pass 1: per-thread partial (max, idx) per channel
    #pragma unroll
    for (int j = 0; j < 4; ++j)
        #pragma unroll
        for (int e = 0; e < 2; ++e) {
            int ch = wn * 32 + j * 8 + q2 + e;
            float m = -FLT_MAX; int mi = 0;
            #pragma unroll
            for (int i = 0; i < 4; ++i) {
                int p0 = pbase + i * 16 + gq;
                float v0 = acc[i][j][e];
                float v1 = acc[i][j][e + 2];
                if (v0 > m) { m = v0; mi = p0; }
                if (v1 > m) { m = v1; mi = p0 + 8; }
            }
            sval[ch * 17 + rowgrp] = m;
            sidx[ch * 17 + rowgrp] = mi;
        }
    __syncthreads();

    // reduce 16 partials; slot 0 = the block max itself (guaranteed kept)
    if (tid < 128) {
        float bv = -FLT_MAX; int bi = 0;
        #pragma unroll
        for (int r = 0; r < 16; ++r) {
            float v  = sval[tid * 17 + r];
            int   ii = sidx[tid * 17 + r];
            if (v > bv || (v == bv && ii < bi)) { bv = v; bi = ii; }
        }
        sbm[tid]  = bv;
        sbi[tid]  = bi;
        scnt[tid] = 1;
        scv[tid * MAXC] = bv;
        scp[tid * MAXC] = bi;
    }
    __syncthreads();

    // pass 2: collect other candidates within MARGIN of block max
    #pragma unroll
    for (int j = 0; j < 4; ++j)
        #pragma unroll
        for (int e = 0; e < 2; ++e) {
            int ch = wn * 32 + j * 8 + q2 + e;
            float thr = sbm[ch] - MARGIN;
            int   bi  = sbi[ch];
            #pragma unroll
            for (int i = 0; i < 4; ++i) {
                int p0 = pbase + i * 16 + gq;
                float v0 = acc[i][j][e];
                float v1 = acc[i][j][e + 2];
                if (v0 > thr && p0 != bi) {
                    int slot = atomicAdd(&scnt[ch], 1);
                    if (slot < MAXC) { scv[ch * MAXC + slot] = v0; scp[ch * MAXC + slot] = p0; }
                }
                if (v1 > thr && (p0 + 8) != bi) {
                    int slot = atomicAdd(&scnt[ch], 1);
                    if (slot < MAXC) { scv[ch * MAXC + slot] = v1; scp[ch * MAXC + slot] = p0 + 8; }
                }
            }
        }
    __syncthreads();

    if (tid < 128) {
        int o = (b * NMT + mt) * NC + nt * 128 + tid;
        int n = min(scnt[tid], MAXC);
        g_smax[o] = sbm[tid];
        g_scnt[o] = n;
        for (int i = 0; i < n; ++i) {
            g_cval[(size_t)o * MAXC + i] = scv[tid * MAXC + i];
            g_cpos[(size_t)o * MAXC + i] = scp[tid * MAXC + i];
        }
    }
}

// ---------------------------------------------------------------------------
// Merge + scatter fused: warp per (b,c); lane l owns m-tile l (NMT == 32).
// All tile loads issue in parallel (MLP=32); ballot+shfl drives the ~1-2
// exact fp32 warp-cooperative rescores; winner row is atomically scattered.
// ---------------------------------------------------------------------------
__global__ __launch_bounds__(256)
void merge_scatter_kernel(const float* __restrict__ x,
                          const float* __restrict__ kern,
                          float* __restrict__ out) {
    int task = blockIdx.x * 8 + (threadIdx.x >> 5);   // 1024 blocks * 8 warps
    int lane = threadIdx.x & 31;
    int b = task >> 9, c = task & (NC - 1);

    const int o = (b * NMT + lane) * NC + c;          // lane's m-tile summary
    float tmax = g_smax[o];
    int   cnt  = g_scnt[o];

    float gmax = tmax;
    #pragma unroll
    for (int off = 16; off > 0; off >>= 1)
        gmax = fmaxf(gmax, __shfl_xor_sync(0xffffffffu, gmax, off));
    const float thr = gmax - MARGIN;

    const float* kr = kern + (size_t)c * ND;
    float4 k4a = *(const float4*)&kr[lane * 8];
    float4 k4b = *(const float4*)&kr[lane * 8 + 4];

    float bestv = -FLT_MAX; int bestp = 0x7fffffff; bool have = false;

    #pragma unroll
    for (int i = 0; i < MAXC; ++i) {
        bool act = (i < cnt);
        float cv = act ? g_cval[(size_t)o * MAXC + i] : -FLT_MAX;
        int   cp = act ? g_cpos[(size_t)o * MAXC + i] : 0;
        unsigned mask = __ballot_sync(0xffffffffu, act && cv > thr);
        while (mask) {
            int l = __ffs(mask) - 1; mask &= mask - 1;
            int p = __shfl_sync(0xffffffffu, cp, l);
            const float* xr = x + ((size_t)b * NP + p) * ND + lane * 8;
            float4 xa = *(const float4*)xr;
            float4 xb = *(const float4*)(xr + 4);
            float sum = xa.x * k4a.x + xa.y * k4a.y + xa.z * k4a.z + xa.w * k4a.w
                      + xb.x * k4b.x + xb.y * k4b.y + xb.z * k4b.z + xb.w * k4b.w;
            #pragma unroll
            for (int off = 16; off > 0; off >>= 1)
                sum += __shfl_xor_sync(0xffffffffu, sum, off);
            if (!have || sum > bestv || (sum == bestv && p < bestp)) {
                bestv = sum; bestp = p; have = true;
            }
        }
    }
    if (bestv <= 0.f) bestp = 0;   // all-ReLU-zero => argmax = 0

    // fused scatter: warp-cooperative atomicAdd of the kernel row
    float* dst = out + ((size_t)b * NP + bestp) * ND + lane * 8;
    atomicAdd(&dst[0], k4a.x); atomicAdd(&dst[1], k4a.y);
    atomicAdd(&dst[2], k4a.z); atomicAdd(&dst[3], k4a.w);
    atomicAdd(&dst[4], k4b.x); atomicAdd(&dst[5], k4b.y);
    atomicAdd(&dst[6], k4b.z); atomicAdd(&dst[7], k4b.w);
}

// ---------------------------------------------------------------------------
extern "C" void kernel_launch(void* const* d_in, const int* in_sizes, int n_in,
                              void* d_out, int out_size) {
    const float* x    = (const float*)d_in[0];
    const float* kern = (const float*)d_in[1];
    float*       out  = (float*)d_out;

    zero_kernel<<<4096, 256>>>((float4*)out, BSZ * NP * ND / 4);

    convert_kernel<<<16513, 256>>>(x, kern);

    size_t smem = 2 * 2 * 128 * LDT * sizeof(__nv_bfloat16);   // 73,728 B
    cudaFuncSetAttribute(gemm_kernel,
                         cudaFuncAttributeMaxDynamicSharedMemorySize, (int)smem);
    gemm_kernel<<<dim3(4, NMT, BSZ), 256, smem>>>();

    merge_scatter_kernel<<<BSZ * NC / 8, 256>>>(x, kern, out);
}